// round 6
// baseline (speedup 1.0000x reference)
#include <cuda_runtime.h>
#include <cstdint>

// ---------------------------------------------------------------------------
// RSSMCore: T=64 sequential steps, B=256.
// Round-6 model:
//  * RNG: jax_threefry_partitionable=True (modern JAX default!). Per flat
//    element i: (o0,o1) = threefry2x32(folded_key, 0, i); bits = o0 ^ o1.
//    (Legacy split-iota layout was the round-1..5 bug: every sample wrong ->
//    precision-independent rel_err plateau 0.3223.)
//  * GEMM: exact f32, per-output ascending-k single-accumulator FMA chain.
//  * z = one_hot + p - stop_grad(p): selected entry = fl(1+p)-p in
//    {1, 1-2^-24} -> carry exact weight into the W_in gather (ascending k:
//    cat rows 0..31 then action row 1024+a; zero entries are exact no-ops).
//  * Elementwise: XLA rational tanh, logistic = 0.5+0.5*tanh(0.5x),
//    cephes-style exp/log, FMA-contracted polynomials (XLA:CPU contraction).
//  * Sampling: gumbel = -log(-log(max(tiny, u+tiny))), first-max argmax.
// ---------------------------------------------------------------------------

#define T_STEPS 64
#define B 256
#define GRU_H 2048
#define MLP 1000
#define ZF 1024
#define FDIM 1024
#define G3 (3 * GRU_H)   // 6144

// ---------------- scratch (device globals; no allocation allowed) ----------
__device__ float g_x[B * MLP];
__device__ float g_gi[B * G3];
__device__ float g_gh[B * G3];
__device__ float g_h[B * GRU_H];
__device__ float g_p1[B * MLP];
__device__ float g_q1[B * MLP];
__device__ float g_cat[B * (GRU_H + FDIM)];
__device__ int   g_zidx[B * 32];
__device__ float g_zw[B * 32];

// =================== XLA-matched elementwise math (FMA form) ================

// XLA EmitTanh rational approx: |x|<0.0004 -> x; clamp +-7.90531110763549805.
__device__ __forceinline__ float xla_tanh(float x) {
    if (fabsf(x) < 0.0004f) return x;
    float xc = fminf(fmaxf(x, -7.90531110763549805f), 7.90531110763549805f);
    float x2 = __fmul_rn(xc, xc);
    float p = -2.76076847742355e-16f;
    p = __fmaf_rn(p, x2, 2.00018790482477e-13f);
    p = __fmaf_rn(p, x2, -8.60467152213735e-11f);
    p = __fmaf_rn(p, x2, 5.12229709037114e-08f);
    p = __fmaf_rn(p, x2, 1.48572235717979e-05f);
    p = __fmaf_rn(p, x2, 6.37261928875436e-04f);
    p = __fmaf_rn(p, x2, 4.89352455891786e-03f);
    p = __fmul_rn(p, xc);
    float q = 1.19825839466702e-06f;
    q = __fmaf_rn(q, x2, 1.18534705686654e-04f);
    q = __fmaf_rn(q, x2, 2.26843463243900e-03f);
    q = __fmaf_rn(q, x2, 4.89352518554385e-03f);
    return __fdiv_rn(p, q);
}

// logistic(x) = 0.5 + 0.5 * tanh(0.5 * x)
__device__ __forceinline__ float xla_sigmoid(float x) {
    return __fmaf_rn(0.5f, xla_tanh(__fmul_rn(0.5f, x)), 0.5f);
}

// cephes-style log (normal positive inputs)
__device__ __forceinline__ float xla_log(float a) {
    int ix = __float_as_int(a);
    float e = (float)((ix >> 23) - 126);
    float m = __int_as_float((ix & 0x007fffff) | 0x3f000000);  // [0.5, 1)
    if (m < 0.707106781186547524f) { e = __fadd_rn(e, -1.0f); m = __fadd_rn(m, m); }
    m = __fadd_rn(m, -1.0f);
    float z = __fmul_rn(m, m);
    float y = 7.0376836292e-2f;
    y = __fmaf_rn(y, m, -1.1514610310e-1f);
    y = __fmaf_rn(y, m, 1.1676998740e-1f);
    y = __fmaf_rn(y, m, -1.2420140846e-1f);
    y = __fmaf_rn(y, m, 1.4249322787e-1f);
    y = __fmaf_rn(y, m, -1.6668057665e-1f);
    y = __fmaf_rn(y, m, 2.0000714765e-1f);
    y = __fmaf_rn(y, m, -2.4999993993e-1f);
    y = __fmaf_rn(y, m, 3.3333331174e-1f);
    y = __fmul_rn(__fmul_rn(y, m), z);
    y = __fmaf_rn(e, -2.12194440e-4f, y);
    y = __fmaf_rn(z, -0.5f, y);
    float r = __fadd_rn(m, y);
    r = __fmaf_rn(e, 0.693359375f, r);
    return r;
}

// cephes-style exp
__device__ __forceinline__ float xla_exp(float x) {
    float xc = fminf(fmaxf(x, -87.33654f), 88.72283f);
    float m = floorf(__fmaf_rn(xc, 1.44269504088896341f, 0.5f));
    float r = __fmaf_rn(m, -0.693359375f, xc);
    r = __fmaf_rn(m, 2.12194440e-4f, r);
    float r2 = __fmul_rn(r, r);
    float p = 1.9875691500e-4f;
    p = __fmaf_rn(p, r, 1.3981999507e-3f);
    p = __fmaf_rn(p, r, 8.3334519073e-3f);
    p = __fmaf_rn(p, r, 4.1665795894e-2f);
    p = __fmaf_rn(p, r, 1.6666665459e-1f);
    p = __fmaf_rn(p, r, 5.0000001201e-1f);
    float y = __fadd_rn(__fmaf_rn(p, r2, r), 1.0f);
    return __fmul_rn(y, __int_as_float(((int)m + 127) << 23));
}

// expm1 (elu negative branch)
__device__ __forceinline__ float xla_expm1(float x) {
    if (fabsf(x) < 1e-5f) return __fmaf_rn(__fmul_rn(0.5f, x), x, x);
    return __fadd_rn(xla_exp(x), -1.0f);
}

__device__ __forceinline__ float xla_elu(float x) {
    return (x > 0.0f) ? x : xla_expm1(x);
}

// ---------------- threefry2x32 (JAX bit-exact) ------------------------------
__device__ __forceinline__ uint32_t rotl32(uint32_t v, int r) {
    return (v << r) | (v >> (32 - r));
}

__device__ __forceinline__ void threefry2x32(uint32_t k0, uint32_t k1,
                                             uint32_t x0, uint32_t x1,
                                             uint32_t& o0, uint32_t& o1) {
    uint32_t ks2 = k0 ^ k1 ^ 0x1BD11BDAu;
    x0 += k0; x1 += k1;
    x0 += x1; x1 = rotl32(x1, 13); x1 ^= x0;
    x0 += x1; x1 = rotl32(x1, 15); x1 ^= x0;
    x0 += x1; x1 = rotl32(x1, 26); x1 ^= x0;
    x0 += x1; x1 = rotl32(x1,  6); x1 ^= x0;
    x0 += k1; x1 += ks2 + 1u;
    x0 += x1; x1 = rotl32(x1, 17); x1 ^= x0;
    x0 += x1; x1 = rotl32(x1, 29); x1 ^= x0;
    x0 += x1; x1 = rotl32(x1, 16); x1 ^= x0;
    x0 += x1; x1 = rotl32(x1, 24); x1 ^= x0;
    x0 += ks2; x1 += k0 + 2u;
    x0 += x1; x1 = rotl32(x1, 13); x1 ^= x0;
    x0 += x1; x1 = rotl32(x1, 15); x1 ^= x0;
    x0 += x1; x1 = rotl32(x1, 26); x1 ^= x0;
    x0 += x1; x1 = rotl32(x1,  6); x1 ^= x0;
    x0 += k0; x1 += k1 + 3u;
    x0 += x1; x1 = rotl32(x1, 17); x1 ^= x0;
    x0 += x1; x1 = rotl32(x1, 29); x1 ^= x0;
    x0 += x1; x1 = rotl32(x1, 16); x1 ^= x0;
    x0 += x1; x1 = rotl32(x1, 24); x1 ^= x0;
    x0 += k1; x1 += ks2 + 4u;
    x0 += x1; x1 = rotl32(x1, 13); x1 ^= x0;
    x0 += x1; x1 = rotl32(x1, 15); x1 ^= x0;
    x0 += x1; x1 = rotl32(x1, 26); x1 ^= x0;
    x0 += x1; x1 = rotl32(x1,  6); x1 ^= x0;
    x0 += ks2; x1 += k0 + 5u;
    o0 = x0; o1 = x1;
}

// partitionable random_bits (32-bit): element i -> xor of both output lanes
__device__ __forceinline__ uint32_t jax_bits32(uint32_t k0, uint32_t k1, uint32_t i) {
    uint32_t o0, o1;
    threefry2x32(k0, k1, 0u, i, o0, o1);
    return o0 ^ o1;
}

// ---------------- fp32 SGEMM: ascending-k single-accumulator FMA chain ------
// C[M,N] = act(A[M,K] @ W[K,N] + bias). BM=BN=64, BK=16, 256 thr, 4x4/thread.
__global__ __launch_bounds__(256) void sgemm_kernel(
    const float* __restrict__ A, const float* __restrict__ W,
    const float* __restrict__ bias, float* __restrict__ C,
    int M, int N, int K, int act)
{
    __shared__ float As[16][64];
    __shared__ float Ws[16][64];
    const int bm = blockIdx.x * 64;
    const int bn = blockIdx.y * 64;
    const int tid = threadIdx.x;
    const int tx = tid & 15;
    const int ty = tid >> 4;

    float acc[4][4];
#pragma unroll
    for (int i = 0; i < 4; i++)
#pragma unroll
        for (int j = 0; j < 4; j++) acc[i][j] = 0.f;

    for (int k0 = 0; k0 < K; k0 += 16) {
#pragma unroll
        for (int l = 0; l < 4; l++) {
            int e = tid + l * 256;
            int r = e >> 4, c = e & 15;
            int k = k0 + c;
            float v = 0.f;
            if (k < K) v = A[(size_t)(bm + r) * K + k];
            As[c][r] = v;
        }
#pragma unroll
        for (int l = 0; l < 4; l++) {
            int e = tid + l * 256;
            int r = e >> 6, c = e & 63;
            int k = k0 + r, col = bn + c;
            float v = 0.f;
            if (k < K && col < N) v = W[(size_t)k * N + col];
            Ws[r][c] = v;
        }
        __syncthreads();
#pragma unroll
        for (int kk = 0; kk < 16; kk++) {
            float4 av = *reinterpret_cast<const float4*>(&As[kk][ty * 4]);
            float4 wv = *reinterpret_cast<const float4*>(&Ws[kk][tx * 4]);
            float a_[4] = {av.x, av.y, av.z, av.w};
            float w_[4] = {wv.x, wv.y, wv.z, wv.w};
#pragma unroll
            for (int i = 0; i < 4; i++)
#pragma unroll
                for (int j = 0; j < 4; j++)
                    acc[i][j] = __fmaf_rn(a_[i], w_[j], acc[i][j]);
        }
        __syncthreads();
    }
#pragma unroll
    for (int i = 0; i < 4; i++) {
        int row = bm + ty * 4 + i;
#pragma unroll
        for (int j = 0; j < 4; j++) {
            int col = bn + tx * 4 + j;
            if (col < N) {
                float v = acc[i][j];
                if (bias) v = __fadd_rn(v, bias[col]);
                if (act) v = xla_elu(v);
                C[(size_t)row * N + col] = v;
            }
        }
    }
}

// ---------------- x = elu(weighted gather of W_in rows + b_in) -------------
// Ascending-k chain over nonzeros: cat rows 0..31 (weight w_c), then the
// action row 1024+a (weight exactly 1.0), then the bias.
__global__ __launch_bounds__(256) void compute_x_kernel(
    const float* __restrict__ W_in, const float* __restrict__ b_in,
    const int* __restrict__ actions, int t)
{
    int b = blockIdx.x;
    int a = (t == 0) ? 0 : actions[(t - 1) * B + b];
    __shared__ int idx[32];
    __shared__ float wgt[32];
    if (threadIdx.x < 32) {
        idx[threadIdx.x] = (t == 0) ? 0 : g_zidx[b * 32 + threadIdx.x];
        wgt[threadIdx.x] = (t == 0) ? 0.f : g_zw[b * 32 + threadIdx.x];
    }
    __syncthreads();
    for (int j = threadIdx.x; j < MLP; j += blockDim.x) {
        float s = 0.f;
        if (t > 0) {
#pragma unroll
            for (int c = 0; c < 32; c++)
                s = __fmaf_rn(wgt[c], W_in[(size_t)(c * 32 + idx[c]) * MLP + j], s);
        }
        s = __fmaf_rn(1.0f, W_in[(size_t)(ZF + a) * MLP + j], s);
        s = __fadd_rn(s, b_in[j]);
        g_x[b * MLP + j] = xla_elu(s);
    }
}

// ---------------- GRU gate pointwise ----------------------------------------
__global__ __launch_bounds__(256) void gru_kernel()
{
    int i = blockIdx.x * blockDim.x + threadIdx.x;  // [0, B*GRU_H)
    int b = i >> 11, j = i & (GRU_H - 1);
    const float* gib = g_gi + (size_t)b * G3;
    const float* ghb = g_gh + (size_t)b * G3;
    float ir = gib[j],              hr = ghb[j];
    float iz = gib[GRU_H + j],      hz = ghb[GRU_H + j];
    float in_ = gib[2 * GRU_H + j], hn = ghb[2 * GRU_H + j];
    float r  = xla_sigmoid(__fadd_rn(ir, hr));
    float zg = xla_sigmoid(__fadd_rn(iz, hz));
    float n  = xla_tanh(__fmaf_rn(r, hn, in_));
    float hp = g_h[i];
    g_h[i] = __fmaf_rn(zg, hp, __fmul_rn(__fsub_rn(1.0f, zg), n));
}

// ---------------- concat [h | feat_t] ---------------------------------------
__global__ __launch_bounds__(256) void concat_kernel(const float* __restrict__ feat_t)
{
    int i = blockIdx.x * blockDim.x + threadIdx.x;  // [0, B*3072)
    int b = i / (GRU_H + FDIM);
    int j = i - b * (GRU_H + FDIM);
    float v = (j < GRU_H) ? g_h[b * GRU_H + j] : feat_t[b * FDIM + (j - GRU_H)];
    g_cat[i] = v;
}

__global__ __launch_bounds__(256) void zero_h_kernel()
{
    int i = blockIdx.x * blockDim.x + threadIdx.x;
    if (i < B * GRU_H) g_h[i] = 0.f;
}

// ---------------- categorical sample + straight-through weight --------------
// Partitionable bits; gumbel; first-max argmax; softmax -> w = fl(1+p)-p.
__global__ __launch_bounds__(256) void sample_kernel(
    const float* __restrict__ post, int t)
{
    int b = blockIdx.x;
    int warp = threadIdx.x >> 5;
    int lane = threadIdx.x & 31;
    uint32_t k0, k1;
    threefry2x32(0u, 42u, 0u, (uint32_t)t, k0, k1);   // fold_in(key(42), t)

    const float TINY = 1.1754943508222875e-38f;

    for (int c = warp; c < 32; c += 8) {
        float l = post[(size_t)b * ZF + c * 32 + lane];

        // partitionable random bits for flat element i of shape (B,32,32)
        uint32_t i = (uint32_t)((b * 32 + c) * 32 + lane);
        uint32_t bits = jax_bits32(k0, k1, i);
        float f = __fadd_rn(__uint_as_float((bits >> 9) | 0x3f800000u), -1.0f);
        float u = fmaxf(TINY, __fadd_rn(f, TINY));
        float g = -xla_log(-xla_log(u));
        float v = __fadd_rn(l, g);

        // first-max-wins argmax over the 32 classes
        float bv = v; int bi = lane;
#pragma unroll
        for (int off = 16; off > 0; off >>= 1) {
            float ov = __shfl_down_sync(0xffffffffu, bv, off);
            int   oi = __shfl_down_sync(0xffffffffu, bi, off);
            if (ov > bv || (ov == bv && oi < bi)) { bv = ov; bi = oi; }
        }
        bi = __shfl_sync(0xffffffffu, bi, 0);

        // softmax prob of selected class: m=max(l); e=exp(l-m); s=sum; p=e/s
        float m = l;
#pragma unroll
        for (int off = 16; off > 0; off >>= 1)
            m = fmaxf(m, __shfl_xor_sync(0xffffffffu, m, off));
        float e = xla_exp(__fadd_rn(l, -m));
        float s = 0.f;
#pragma unroll
        for (int ll = 0; ll < 32; ll++)
            s = __fadd_rn(s, __shfl_sync(0xffffffffu, e, ll));
        float p = __fdiv_rn(e, s);
        float psel = __shfl_sync(0xffffffffu, p, bi);
        if (lane == 0) {
            float w = __fadd_rn(__fadd_rn(1.0f, psel), -psel);  // fl(1+p)-p
            g_zidx[b * 32 + c] = bi;
            g_zw[b * 32 + c] = w;
        }
    }
}

// ---------------------------------------------------------------------------
extern "C" void kernel_launch(void* const* d_in, const int* in_sizes, int n_in,
                              void* d_out, int out_size)
{
    const float* features = (const float*)d_in[0];   // [64,256,1024]
    const int*   actions  = (const int*)  d_in[1];   // [64,256]
    const float* W_in = (const float*)d_in[2];       // [1030,1000]
    const float* b_in = (const float*)d_in[3];
    const float* W_ih = (const float*)d_in[4];       // [1000,6144]
    const float* W_hh = (const float*)d_in[5];       // [2048,6144]
    const float* b_ih = (const float*)d_in[6];
    const float* b_hh = (const float*)d_in[7];
    const float* Wp1  = (const float*)d_in[8];       // [2048,1000]
    const float* bp1  = (const float*)d_in[9];
    const float* Wp2  = (const float*)d_in[10];      // [1000,1024]
    const float* bp2  = (const float*)d_in[11];
    const float* Wq1  = (const float*)d_in[12];      // [3072,1000]
    const float* bq1  = (const float*)d_in[13];
    const float* Wq2  = (const float*)d_in[14];      // [1000,1024]
    const float* bq2  = (const float*)d_in[15];
    float* out = (float*)d_out;                      // [2,64,256,32,32]

    float *px, *pgi, *pgh, *ph, *pp1, *pq1, *pcat;
    cudaGetSymbolAddress((void**)&px,  g_x);
    cudaGetSymbolAddress((void**)&pgi, g_gi);
    cudaGetSymbolAddress((void**)&pgh, g_gh);
    cudaGetSymbolAddress((void**)&ph,  g_h);
    cudaGetSymbolAddress((void**)&pp1, g_p1);
    cudaGetSymbolAddress((void**)&pq1, g_q1);
    cudaGetSymbolAddress((void**)&pcat, g_cat);

    zero_h_kernel<<<(B * GRU_H + 255) / 256, 256>>>();

    for (int t = 0; t < T_STEPS; t++) {
        const float* feat_t = features + (size_t)t * B * FDIM;
        float* out_prior = out + (size_t)t * B * ZF;
        float* out_post  = out + ((size_t)(T_STEPS + t)) * B * ZF;

        compute_x_kernel<<<B, 256>>>(W_in, b_in, actions, t);

        sgemm_kernel<<<dim3(B / 64, G3 / 64), 256>>>(px, W_ih, b_ih, pgi, B, G3, MLP, 0);
        sgemm_kernel<<<dim3(B / 64, G3 / 64), 256>>>(ph, W_hh, b_hh, pgh, B, G3, GRU_H, 0);

        gru_kernel<<<(B * GRU_H) / 256, 256>>>();

        sgemm_kernel<<<dim3(B / 64, (MLP + 63) / 64), 256>>>(ph, Wp1, bp1, pp1, B, MLP, GRU_H, 1);
        sgemm_kernel<<<dim3(B / 64, ZF / 64), 256>>>(pp1, Wp2, bp2, out_prior, B, ZF, MLP, 0);

        concat_kernel<<<(B * (GRU_H + FDIM)) / 256, 256>>>(feat_t);
        sgemm_kernel<<<dim3(B / 64, (MLP + 63) / 64), 256>>>(pcat, Wq1, bq1, pq1, B, MLP, GRU_H + FDIM, 1);
        sgemm_kernel<<<dim3(B / 64, ZF / 64), 256>>>(pq1, Wq2, bq2, out_post, B, ZF, MLP, 0);

        sample_kernel<<<B, 256>>>(out_post, t);
    }
}